// round 1
// baseline (speedup 1.0000x reference)
#include <cuda_runtime.h>

// Bilateral filter 9x9, sigma_s=3, sigma_r=0.1, reflect padding, 4096x4096 fp32.
//
// Math: w = spatial * exp(-(win-c)^2 / (2*sr^2))
// Fold into a single exp2: w = exp2( Ls(dy,dx) - (win-c)^2 * K2 )
//   K2 = log2(e) / (2*0.1^2) = 50*log2(e)
//   Ls = -((dx-4)^2+(dy-4)^2) / 18 * log2(e)
// Expand the square to save ops (and enable FFMA-imm rt=1 form):
//   arg = (-K2*win + a)*win + (base + Ls),  a = 2*K2*c,  base = -K2*c*c

#define IMG_H 4096
#define IMG_W 4096
#define RAD 4
#define BX 32
#define BY 8
#define TW (BX + 2*RAD)   // 40
#define TH (BY + 2*RAD)   // 16

__device__ __forceinline__ float ex2f(float x) {
    float y;
    asm("ex2.approx.f32 %0, %1;" : "=f"(y) : "f"(x));
    return y;
}

__global__ __launch_bounds__(BX * BY)
void bilateral_kernel(const float* __restrict__ img, float* __restrict__ out) {
    __shared__ float tile[TH][TW];

    const int tx = threadIdx.x;
    const int ty = threadIdx.y;
    const int bx0 = blockIdx.x * BX;
    const int by0 = blockIdx.y * BY;
    const int tid = ty * BX + tx;

    // Cooperative tile load with reflect padding (jnp 'reflect': -1 -> 1, H -> H-2)
    #pragma unroll
    for (int i = tid; i < TH * TW; i += BX * BY) {
        int r = i / TW;
        int c = i - r * TW;
        int gy = by0 + r - RAD;
        int gx = bx0 + c - RAD;
        gy = (gy < 0) ? -gy : ((gy >= IMG_H) ? (2 * IMG_H - 2 - gy) : gy);
        gx = (gx < 0) ? -gx : ((gx >= IMG_W) ? (2 * IMG_W - 2 - gx) : gx);
        tile[r][c] = img[gy * IMG_W + gx];
    }
    __syncthreads();

    const float K2 = 72.13475204444817f;           // 50 * log2(e)
    const float LOG2E_OVER_S = 1.4426950408889634f / 18.0f;

    const float cval = tile[ty + RAD][tx + RAD];
    const float a    = 2.0f * K2 * cval;
    const float base = -K2 * cval * cval;

    float num = 0.0f;
    float den = 0.0f;

    #pragma unroll
    for (int dy = 0; dy < 9; dy++) {
        #pragma unroll
        for (int dx = 0; dx < 9; dx++) {
            const float win = tile[ty + dy][tx + dx];
            // compile-time constant spatial log2-weight; (base + Ls) is CSE'd
            // across taps to 15 distinct adds (15 distinct squared distances)
            const float Ls = -(float)((dx - 4) * (dx - 4) + (dy - 4) * (dy - 4)) * LOG2E_OVER_S;
            const float btap = base + Ls;
            const float t   = fmaf(-K2, win, a);     // FFMA with imm multiplier (rt=1)
            const float arg = fmaf(win, t, btap);    // FFMA
            const float w   = ex2f(arg);             // MUFU.EX2
            num = fmaf(w, win, num);                 // FFMA
            den += w;                                // FADD
        }
    }

    out[(by0 + ty) * IMG_W + (bx0 + tx)] = __fdividef(num, den);
}

extern "C" void kernel_launch(void* const* d_in, const int* in_sizes, int n_in,
                              void* d_out, int out_size) {
    const float* img = (const float*)d_in[0];
    float* out = (float*)d_out;
    dim3 block(BX, BY);
    dim3 grid(IMG_W / BX, IMG_H / BY);
    bilateral_kernel<<<grid, block>>>(img, out);
}